// round 1
// baseline (speedup 1.0000x reference)
#include <cuda_runtime.h>

// NLinear: out[b,n,o] = sum_i x[b,n,i] * W[n,i,o] + bias[n,o]
// Shapes: x[256,128,512] f32, W[128,512,512] f32, bias[128,512] f32, out[256,128,512] f32
// Per-n GEMM: C[256,512] = X[256,512] @ W[512,512], X/C row stride = 128*512.

#define BM 128
#define BN 128
#define BK 16
#define TM 8
#define TN 8

static constexpr int N_POS  = 128;
static constexpr int D_IN   = 512;
static constexpr int D_OUT  = 512;
static constexpr int BATCH  = 256;
static constexpr int XSTRIDE = N_POS * D_IN;   // row stride of X (floats)
static constexpr int CSTRIDE = N_POS * D_OUT;  // row stride of C (floats)

__global__ __launch_bounds__(256, 2)
void nlinear_sgemm_kernel(const float* __restrict__ x,
                          const float* __restrict__ w,
                          const float* __restrict__ bias,
                          float* __restrict__ out)
{
    const int n  = blockIdx.z;   // position 0..127
    const int bm = blockIdx.y;   // 0..1  (BATCH/BM)
    const int bn = blockIdx.x;   // 0..3  (D_OUT/BN)

    __shared__ float As[BK][BM];   // A transposed: As[k][m]
    __shared__ float Bs[BK][BN];   // Bs[k][o]

    const int tid = threadIdx.x;
    const int tx  = tid & 15;   // output-col group
    const int ty  = tid >> 4;   // output-row group

    // Base pointers for this block's tile
    const float* A  = x + ((size_t)(bm * BM) * N_POS + n) * D_IN;          // [BM rows, stride XSTRIDE]
    const float* Bw = w + (size_t)n * D_IN * D_OUT + (size_t)bn * BN;      // [D_IN rows, stride D_OUT]
    float*       C  = out + ((size_t)(bm * BM) * N_POS + n) * D_OUT + (size_t)bn * BN;

    float acc[TM][TN];
    #pragma unroll
    for (int i = 0; i < TM; i++)
        #pragma unroll
        for (int j = 0; j < TN; j++)
            acc[i][j] = 0.0f;

    for (int k0 = 0; k0 < D_IN; k0 += BK) {
        // ---- Load A tile: BM x BK = 2048 floats = 512 float4, 2 per thread ----
        #pragma unroll
        for (int l = 0; l < 2; l++) {
            int f   = tid * 2 + l;          // 0..511
            int ar  = f >> 2;               // row in tile 0..127
            int ac4 = (f & 3) * 4;          // k offset 0/4/8/12
            float4 va = *(const float4*)(A + (size_t)ar * XSTRIDE + k0 + ac4);
            As[ac4 + 0][ar] = va.x;
            As[ac4 + 1][ar] = va.y;
            As[ac4 + 2][ar] = va.z;
            As[ac4 + 3][ar] = va.w;

            // ---- Load B tile: BK x BN = 2048 floats = 512 float4 ----
            int br  = f >> 5;               // k row 0..15
            int bc4 = (f & 31) * 4;         // col 0..124
            float4 vb = *(const float4*)(Bw + (size_t)(k0 + br) * D_OUT + bc4);
            *(float4*)&Bs[br][bc4] = vb;
        }
        __syncthreads();

        // ---- Compute: 16 k-steps, 8x8 FMA per thread per step ----
        #pragma unroll
        for (int k = 0; k < BK; k++) {
            float af[TM], bf[TN];
            // vectorized shared loads (32B aligned)
            float4 a0 = *(const float4*)&As[k][ty * TM + 0];
            float4 a1 = *(const float4*)&As[k][ty * TM + 4];
            af[0] = a0.x; af[1] = a0.y; af[2] = a0.z; af[3] = a0.w;
            af[4] = a1.x; af[5] = a1.y; af[6] = a1.z; af[7] = a1.w;
            float4 b0 = *(const float4*)&Bs[k][tx * TN + 0];
            float4 b1 = *(const float4*)&Bs[k][tx * TN + 4];
            bf[0] = b0.x; bf[1] = b0.y; bf[2] = b0.z; bf[3] = b0.w;
            bf[4] = b1.x; bf[5] = b1.y; bf[6] = b1.z; bf[7] = b1.w;

            #pragma unroll
            for (int i = 0; i < TM; i++)
                #pragma unroll
                for (int j = 0; j < TN; j++)
                    acc[i][j] = fmaf(af[i], bf[j], acc[i][j]);
        }
        __syncthreads();
    }

    // ---- Epilogue: add bias, vectorized store ----
    const float* bp = bias + (size_t)n * D_OUT + (size_t)bn * BN + tx * TN;
    float4 bv0 = *(const float4*)(bp + 0);
    float4 bv1 = *(const float4*)(bp + 4);

    #pragma unroll
    for (int i = 0; i < TM; i++) {
        int row = ty * TM + i;
        float4 v0, v1;
        v0.x = acc[i][0] + bv0.x;
        v0.y = acc[i][1] + bv0.y;
        v0.z = acc[i][2] + bv0.z;
        v0.w = acc[i][3] + bv0.w;
        v1.x = acc[i][4] + bv1.x;
        v1.y = acc[i][5] + bv1.y;
        v1.z = acc[i][6] + bv1.z;
        v1.w = acc[i][7] + bv1.w;
        float* cp = C + (size_t)row * CSTRIDE + tx * TN;
        *(float4*)(cp + 0) = v0;
        *(float4*)(cp + 4) = v1;
    }
}

extern "C" void kernel_launch(void* const* d_in, const int* in_sizes, int n_in,
                              void* d_out, int out_size)
{
    const float* x    = (const float*)d_in[0];   // [256,128,512]
    const float* w    = (const float*)d_in[1];   // [128,512,512]
    const float* bias = (const float*)d_in[2];   // [128,512]
    float* out        = (float*)d_out;           // [256,128,512]

    dim3 grid(D_OUT / BN, BATCH / BM, N_POS);    // (4, 2, 128)
    dim3 block(256);
    nlinear_sgemm_kernel<<<grid, block>>>(x, w, bias, out);
}

// round 3
// speedup vs baseline: 3.7228x; 3.7228x over previous
#include <cuda_runtime.h>
#include <cstdint>

// NLinear via mma.sync tf32 (base sm_100 target — tcgen05 unavailable).
// out[b,n,o] = sum_i x[b,n,i]*W[n,i,o] + bias[n,o]
// x[256,128,512] f32, W[128,512,512] f32, bias[128,512] f32, out[256,128,512] f32
// Per-n GEMM: C[256,512] = X[256,512] @ W[512,512].

static constexpr int N_POS = 128;
static constexpr int D_IN  = 512;
static constexpr int D_OUT = 512;
static constexpr int BATCH = 256;
static constexpr int XSTR  = N_POS * D_IN;   // 65536: batch-row stride in x/out
static constexpr int WSTR  = D_IN * D_OUT;   // 262144

static constexpr int BM = 128;
static constexpr int BN = 128;
static constexpr int BK = 32;
static constexpr int KITERS = D_IN / BK;     // 16

static constexpr int APAD = 4;
static constexpr int BPAD = 4;
static constexpr int ASTR = BK + APAD;       // 36 floats
static constexpr int BSTR = BN + BPAD;       // 132 floats
static constexpr int A_ELEMS = BM * ASTR;    // 4608
static constexpr int B_ELEMS = BK * BSTR;    // 4224
static constexpr int STAGE   = A_ELEMS + B_ELEMS;  // 8832 floats
static constexpr int SMEM_BYTES = 2 * STAGE * 4;   // 70656

__device__ __forceinline__ void cp16(float* dst_smem, const float* src) {
    uint32_t d = (uint32_t)__cvta_generic_to_shared(dst_smem);
    asm volatile("cp.async.cg.shared.global [%0], [%1], 16;" :: "r"(d), "l"(src));
}
__device__ __forceinline__ void cp_commit() {
    asm volatile("cp.async.commit_group;" ::: "memory");
}
template <int N>
__device__ __forceinline__ void cp_wait() {
    asm volatile("cp.async.wait_group %0;" :: "n"(N) : "memory");
}
__device__ __forceinline__ uint32_t f2tf32(float f) {
    uint32_t r;
    asm("cvt.rna.tf32.f32 %0, %1;" : "=r"(r) : "f"(f));
    return r;
}
__device__ __forceinline__ void mma_tf32(float c[4],
                                         const uint32_t a[4],
                                         const uint32_t b[2]) {
    asm volatile(
        "mma.sync.aligned.m16n8k8.row.col.f32.tf32.tf32.f32 "
        "{%0,%1,%2,%3}, {%4,%5,%6,%7}, {%8,%9}, {%0,%1,%2,%3};"
        : "+f"(c[0]), "+f"(c[1]), "+f"(c[2]), "+f"(c[3])
        : "r"(a[0]), "r"(a[1]), "r"(a[2]), "r"(a[3]), "r"(b[0]), "r"(b[1]));
}

__device__ __forceinline__ void prefetch_stage(float* sm, int stage,
                                               const float* xb, const float* wb,
                                               int k0, int tid)
{
    float* As = sm + stage * STAGE;
    float* Bs = As + A_ELEMS;
    // A tile: 128 rows x 32 floats (128B/row) = 1024 x 16B chunks
    #pragma unroll
    for (int j = 0; j < 4; j++) {
        int c  = tid + j * 256;
        int m  = c >> 3;
        int kc = c & 7;
        cp16(As + m * ASTR + kc * 4, xb + (size_t)m * XSTR + k0 + kc * 4);
    }
    // B tile: 32 rows x 128 floats (512B/row) = 1024 x 16B chunks
    #pragma unroll
    for (int j = 0; j < 4; j++) {
        int c  = tid + j * 256;
        int kr = c >> 5;
        int nc = c & 31;
        cp16(Bs + kr * BSTR + nc * 4, wb + (size_t)(k0 + kr) * D_OUT + nc * 4);
    }
    cp_commit();
}

__global__ __launch_bounds__(256, 2)
void nlinear_mma_kernel(const float* __restrict__ x,
                        const float* __restrict__ w,
                        const float* __restrict__ bias,
                        float* __restrict__ out)
{
    extern __shared__ float sm[];

    const int tid = threadIdx.x;
    const int wid = tid >> 5;
    const int lid = tid & 31;
    const int g   = lid >> 2;   // group id (row within 8)
    const int t   = lid & 3;    // thread-in-group (k / col pairs)

    const int n     = blockIdx.z;
    const int obase = blockIdx.x * BN;
    const int mbase = blockIdx.y * BM;

    // warp grid 2 (M) x 4 (N): warp tile 64 x 32
    const int wm0 = (wid & 1) * 64;
    const int wn0 = (wid >> 1) * 32;

    const float* xb = x + (size_t)mbase * XSTR + (size_t)n * D_IN;
    const float* wb = w + (size_t)n * WSTR + obase;

    float acc[4][4][4];
    #pragma unroll
    for (int mt = 0; mt < 4; mt++)
        #pragma unroll
        for (int nt = 0; nt < 4; nt++)
            #pragma unroll
            for (int q = 0; q < 4; q++)
                acc[mt][nt][q] = 0.0f;

    prefetch_stage(sm, 0, xb, wb, 0, tid);

    for (int it = 0; it < KITERS; ++it) {
        if (it + 1 < KITERS) {
            prefetch_stage(sm, (it + 1) & 1, xb, wb, (it + 1) * BK, tid);
            cp_wait<1>();
        } else {
            cp_wait<0>();
        }
        __syncthreads();

        const float* As = sm + (it & 1) * STAGE;
        const float* Bs = As + A_ELEMS;

        #pragma unroll
        for (int ks = 0; ks < 4; ks++) {
            const int kk = ks * 8;
            uint32_t a[4][4];
            uint32_t b[4][2];
            #pragma unroll
            for (int mt = 0; mt < 4; mt++) {
                const float* ap = As + (wm0 + 16 * mt + g) * ASTR + kk + t;
                a[mt][0] = f2tf32(ap[0]);
                a[mt][1] = f2tf32(ap[8 * ASTR]);
                a[mt][2] = f2tf32(ap[4]);
                a[mt][3] = f2tf32(ap[8 * ASTR + 4]);
            }
            #pragma unroll
            for (int nt = 0; nt < 4; nt++) {
                const float* bp = Bs + (kk + t) * BSTR + wn0 + 8 * nt + g;
                b[nt][0] = f2tf32(bp[0]);
                b[nt][1] = f2tf32(bp[4 * BSTR]);
            }
            #pragma unroll
            for (int mt = 0; mt < 4; mt++)
                #pragma unroll
                for (int nt = 0; nt < 4; nt++)
                    mma_tf32(acc[mt][nt], a[mt], b[nt]);
        }
        __syncthreads();
    }

    // ---- Epilogue: bias + store (float2, sector-aligned per 4-lane group) ----
    const float* brow = bias + (size_t)n * D_OUT + obase;
    #pragma unroll
    for (int mt = 0; mt < 4; mt++) {
        const int r0 = mbase + wm0 + 16 * mt + g;
        float* o0 = out + (size_t)r0 * XSTR + (size_t)n * D_OUT + obase;
        float* o1 = o0 + (size_t)8 * XSTR;
        #pragma unroll
        for (int nt = 0; nt < 4; nt++) {
            const int col = wn0 + 8 * nt + 2 * t;
            float2 bv = *(const float2*)(brow + col);
            float2 v0, v1;
            v0.x = acc[mt][nt][0] + bv.x;
            v0.y = acc[mt][nt][1] + bv.y;
            v1.x = acc[mt][nt][2] + bv.x;
            v1.y = acc[mt][nt][3] + bv.y;
            *(float2*)(o0 + col) = v0;
            *(float2*)(o1 + col) = v1;
        }
    }
}

extern "C" void kernel_launch(void* const* d_in, const int* in_sizes, int n_in,
                              void* d_out, int out_size)
{
    const float* x    = (const float*)d_in[0];
    const float* w    = (const float*)d_in[1];
    const float* bias = (const float*)d_in[2];
    float* out        = (float*)d_out;

    cudaFuncSetAttribute(nlinear_mma_kernel,
                         cudaFuncAttributeMaxDynamicSharedMemorySize, SMEM_BYTES);

    dim3 grid(D_OUT / BN, BATCH / BM, N_POS);   // (4, 2, 128)
    dim3 block(256);
    nlinear_mma_kernel<<<grid, block, SMEM_BYTES>>>(x, w, bias, out);
}